// round 17
// baseline (speedup 1.0000x reference)
#include <cuda_runtime.h>
#include <cuda_bf16.h>
#include <math.h>
#include <stdint.h>

// Problem constants
#define T_STEPS 100
#define B_SZ    256
#define D_SZ    2048
#define M_TOTAL (T_STEPS * B_SZ)          // 25600
#define BD      (B_SZ * D_SZ)             // 524288

// Reference encoder accumulation (CONFIRMED bit-exact in R16):
// 8 ascending fp32 FMA chains of 256 k, joined sequentially; one bias add.
#define KC_TILES 16

// ---------------- device scratch (no cudaMalloc allowed) -------------------
__device__ float         g_enc[(size_t)M_TOTAL * D_SZ];
__device__ __nv_bfloat16 g_spkb[(size_t)M_TOTAL * D_SZ];   // bf16 copy of spikes
__device__ __nv_bfloat16 g_Wh[(size_t)D_SZ * D_SZ];        // W_dec hi
__device__ __nv_bfloat16 g_Wl[(size_t)D_SZ * D_SZ];        // W_dec lo

// ---------------- packed f32x2 helpers (encoder FFMA2 path) ----------------
typedef unsigned long long u64;

__device__ __forceinline__ u64 pk2(float lo, float hi) {
    u64 r; asm("mov.b64 %0, {%1,%2};" : "=l"(r) : "f"(lo), "f"(hi)); return r;
}
__device__ __forceinline__ void upk2(u64 v, float& lo, float& hi) {
    asm("mov.b64 {%0,%1}, %2;" : "=f"(lo), "=f"(hi) : "l"(v));
}
__device__ __forceinline__ u64 fma2(u64 a, u64 b, u64 d) {
    u64 r; asm("fma.rn.f32x2 %0, %1, %2, %3;" : "=l"(r) : "l"(a), "l"(b), "l"(d)); return r;
}
__device__ __forceinline__ u64 add2(u64 a, u64 b) {
    u64 r; asm("add.rn.f32x2 %0, %1, %2;" : "=l"(r) : "l"(a), "l"(b)); return r;
}

// ---------------------------------------------------------------------------
// ENCODER GEMM — byte-identical accumulation to R16 (bit-exact vs reference).
// C[M,N] = gather(x)[M,K] * W_enc[N,K]^T + bias
// 8x256 sequentially-joined ascending FFMA2 chains per output element.
// ---------------------------------------------------------------------------

__device__ __forceinline__ float4 loadA_enc(const float* __restrict__ x,
                                            int t, int b, int k) {
    int hw = k & 1023;
    int c  = k >> 10;
    return *(const float4*)(x + ((((b << 1) + c) * T_STEPS + t) << 10) + hw);
}

__global__ void __launch_bounds__(256, 1)
gemm_enc_k(const float* __restrict__ A,     // x
           const float* __restrict__ W,     // [N,K]
           const float* __restrict__ bias,  // [N]
           float* __restrict__ Cout)        // [M,N]
{
    const int K = D_SZ;
    __shared__ float As[2][16][132];
    __shared__ float Bs[2][16][132];

    const int tid = threadIdx.x;
    const int m0 = blockIdx.y * 128;
    const int n0 = blockIdx.x * 128;

    const int lr = tid >> 2;            // 0..63
    const int lc = (tid & 3) << 2;      // 0,4,8,12

    const int ma0 = m0 + lr;
    const int ma1 = m0 + lr + 64;
    const int nb0 = n0 + lr;
    const int nb1 = n0 + lr + 64;

    const int ta0 = ma0 >> 8, ba0 = ma0 & 255;
    const int ta1 = ma1 >> 8, ba1 = ma1 & 255;

    const float* wrow0 = W + (size_t)nb0 * K;
    const float* wrow1 = W + (size_t)nb1 * K;

    const int tx8 = (tid & 15) << 3;
    const int ty8 = (tid >> 4) << 3;

    u64 acc[8][4];
    u64 tot[8][4];
#pragma unroll
    for (int i = 0; i < 8; i++)
#pragma unroll
        for (int j = 0; j < 4; j++) { acc[i][j] = 0ULL; tot[i][j] = 0ULL; }

    float4 ra0, ra1, rb0, rb1;

    {
        int k = lc;
        ra0 = loadA_enc(A, ta0, ba0, k);
        ra1 = loadA_enc(A, ta1, ba1, k);
        rb0 = *(const float4*)(wrow0 + k);
        rb1 = *(const float4*)(wrow1 + k);
    }
    As[0][lc + 0][lr] = ra0.x;  As[0][lc + 1][lr] = ra0.y;
    As[0][lc + 2][lr] = ra0.z;  As[0][lc + 3][lr] = ra0.w;
    As[0][lc + 0][lr + 64] = ra1.x;  As[0][lc + 1][lr + 64] = ra1.y;
    As[0][lc + 2][lr + 64] = ra1.z;  As[0][lc + 3][lr + 64] = ra1.w;
    Bs[0][lc + 0][lr] = rb0.x;  Bs[0][lc + 1][lr] = rb0.y;
    Bs[0][lc + 2][lr] = rb0.z;  Bs[0][lc + 3][lr] = rb0.w;
    Bs[0][lc + 0][lr + 64] = rb1.x;  Bs[0][lc + 1][lr + 64] = rb1.y;
    Bs[0][lc + 2][lr + 64] = rb1.z;  Bs[0][lc + 3][lr + 64] = rb1.w;

    int buf = 0;
    const int kIters = K / 16;          // 128

    for (int kt = 0; kt < kIters; kt++) {
        __syncthreads();

        if (kt + 1 < kIters) {
            int k = ((kt + 1) << 4) + lc;
            ra0 = loadA_enc(A, ta0, ba0, k);
            ra1 = loadA_enc(A, ta1, ba1, k);
            rb0 = *(const float4*)(wrow0 + k);
            rb1 = *(const float4*)(wrow1 + k);
        }

#pragma unroll
        for (int kk = 0; kk < 16; kk++) {
            float af[8], bf[8];
            *(float4*)&af[0] = *(const float4*)&As[buf][kk][ty8];
            *(float4*)&af[4] = *(const float4*)&As[buf][kk][ty8 + 4];
            *(float4*)&bf[0] = *(const float4*)&Bs[buf][kk][tx8];
            *(float4*)&bf[4] = *(const float4*)&Bs[buf][kk][tx8 + 4];

            u64 bp[4];
            bp[0] = pk2(bf[0], bf[1]);
            bp[1] = pk2(bf[2], bf[3]);
            bp[2] = pk2(bf[4], bf[5]);
            bp[3] = pk2(bf[6], bf[7]);
#pragma unroll
            for (int i = 0; i < 8; i++) {
                u64 ap = pk2(af[i], af[i]);
#pragma unroll
                for (int j = 0; j < 4; j++)
                    acc[i][j] = fma2(ap, bp[j], acc[i][j]);
            }
        }

        if (((kt + 1) & (KC_TILES - 1)) == 0 && (kt + 1) < kIters) {
#pragma unroll
            for (int i = 0; i < 8; i++)
#pragma unroll
                for (int j = 0; j < 4; j++) {
                    tot[i][j] = add2(tot[i][j], acc[i][j]);
                    acc[i][j] = 0ULL;
                }
        }

        if (kt + 1 < kIters) {
            buf ^= 1;
            As[buf][lc + 0][lr] = ra0.x;  As[buf][lc + 1][lr] = ra0.y;
            As[buf][lc + 2][lr] = ra0.z;  As[buf][lc + 3][lr] = ra0.w;
            As[buf][lc + 0][lr + 64] = ra1.x;  As[buf][lc + 1][lr + 64] = ra1.y;
            As[buf][lc + 2][lr + 64] = ra1.z;  As[buf][lc + 3][lr + 64] = ra1.w;
            Bs[buf][lc + 0][lr] = rb0.x;  Bs[buf][lc + 1][lr] = rb0.y;
            Bs[buf][lc + 2][lr] = rb0.z;  Bs[buf][lc + 3][lr] = rb0.w;
            Bs[buf][lc + 0][lr + 64] = rb1.x;  Bs[buf][lc + 1][lr + 64] = rb1.y;
            Bs[buf][lc + 2][lr + 64] = rb1.z;  Bs[buf][lc + 3][lr + 64] = rb1.w;
        }
    }

    float bv[8];
    *(float4*)&bv[0] = *(const float4*)(bias + n0 + tx8);
    *(float4*)&bv[4] = *(const float4*)(bias + n0 + tx8 + 4);

#pragma unroll
    for (int i = 0; i < 8; i++) {
        int m = m0 + ty8 + i;
        float* crow = Cout + (size_t)m * D_SZ + n0 + tx8;
        float r[8];
#pragma unroll
        for (int j = 0; j < 4; j++) {
            u64 fin = add2(tot[i][j], acc[i][j]);
            float s0, s1;
            upk2(fin, s0, s1);
            r[2 * j]     = __fadd_rn(s0, bv[2 * j]);
            r[2 * j + 1] = __fadd_rn(s1, bv[2 * j + 1]);
        }
        float4 v0, v1;
        v0.x = r[0]; v0.y = r[1]; v0.z = r[2]; v0.w = r[3];
        v1.x = r[4]; v1.y = r[5]; v1.z = r[6]; v1.w = r[7];
        *(float4*)(crow)     = v0;
        *(float4*)(crow + 4) = v1;
    }
}

// ---------------------------------------------------------------------------
// LIF scan: also emits a bf16 spike copy (0/1 exact in bf16) for the decoder.
// ---------------------------------------------------------------------------
__global__ void __launch_bounds__(256)
lif_scan_k(const float* __restrict__ enc,
           const float* __restrict__ beta,
           float* __restrict__ spk_out,
           __nv_bfloat16* __restrict__ spk_b)
{
    int idx = blockIdx.x * blockDim.x + threadIdx.x;   // 0..BD-1
    int d = idx & (D_SZ - 1);
    float bc = fminf(fmaxf(beta[d], 0.0f), 1.0f);

    float mem = 0.0f, sp = 0.0f;
    const float* ep = enc + idx;
    float* op = spk_out + idx;
    __nv_bfloat16* ob = spk_b + idx;

#pragma unroll 4
    for (int t = 0; t < T_STEPS; t++) {
        mem = __fsub_rn(fmaf(bc, mem, ep[(size_t)t * BD]), sp);
        sp  = (mem > 1.0f) ? 1.0f : 0.0f;
        op[(size_t)t * BD] = sp;
        ob[(size_t)t * BD] = __float2bfloat16(sp);   // exact
    }
}

// ---------------------------------------------------------------------------
// W_dec exact 2-way bf16 split: w = hi + lo + eps, |eps| ~ 2^-17 |w|
// ---------------------------------------------------------------------------
__global__ void __launch_bounds__(256)
split_wdec_k(const float* __restrict__ W,
             __nv_bfloat16* __restrict__ h, __nv_bfloat16* __restrict__ l)
{
    size_t idx = (size_t)blockIdx.x * 256 + threadIdx.x;   // over D*D
    float a = W[idx];
    __nv_bfloat16 hh = __float2bfloat16(a);
    float r1 = __fsub_rn(a, __bfloat162float(hh));
    h[idx] = hh;
    l[idx] = __float2bfloat16(r1);
}

// ---------------------------------------------------------------------------
// DECODER via mma.sync bf16x2 (tensor pipe):
//   dec = sigmoid( spk_bf16 @ (Wh + Wl)^T + b_dec )
// spk is exact in bf16; Wh+Wl captures ~16 mantissa bits; fp32 accumulators.
// Output-1 tolerance (1e-3) is ~30-100x above the resulting error.
// Tile 128x128, BK=32, 256 threads (8 warps as 2m x 4n of 64x32).
// ---------------------------------------------------------------------------
#define DROW_B  80              // smem row stride: 32 bf16 = 64B + 16B pad
#define DTILE_B (128 * DROW_B)  // 10240 B
#define DEC_SMEM (3 * DTILE_B)  // spk, Wh, Wl

__device__ __forceinline__ void mma16816(float* c, const uint32_t* a, const uint32_t* b) {
    asm volatile(
        "mma.sync.aligned.m16n8k16.row.col.f32.bf16.bf16.f32 "
        "{%0,%1,%2,%3}, {%4,%5,%6,%7}, {%8,%9}, {%0,%1,%2,%3};"
        : "+f"(c[0]), "+f"(c[1]), "+f"(c[2]), "+f"(c[3])
        : "r"(a[0]), "r"(a[1]), "r"(a[2]), "r"(a[3]), "r"(b[0]), "r"(b[1]));
}

__global__ void __launch_bounds__(256, 1)
dec_mma_k(const __nv_bfloat16* __restrict__ S,   // spk bf16 [M,K]
          const __nv_bfloat16* __restrict__ Wh,  // [N,K]
          const __nv_bfloat16* __restrict__ Wl,  // [N,K]
          const float* __restrict__ bias, float* __restrict__ dec)
{
    extern __shared__ char smem[];

    const int tid = threadIdx.x;
    const int w   = tid >> 5;           // warp 0..7
    const int lid = tid & 31;
    const int wm  = w >> 2;             // 0..1 (64-row half)
    const int wn  = w & 3;              // 0..3 (32-col quarter)

    const int m0 = blockIdx.y * 128;
    const int n0 = blockIdx.x * 128;

    const int fr = lid >> 2;            // 0..7
    const int kp = lid & 3;             // 0..3

    float acc[4][4][4];                 // [mf][nf][4]
#pragma unroll
    for (int i = 0; i < 4; i++)
#pragma unroll
        for (int j = 0; j < 4; j++)
#pragma unroll
            for (int q = 0; q < 4; q++) acc[i][j][q] = 0.0f;

    const int kTiles = D_SZ / 32;       // 64

    for (int kt = 0; kt < kTiles; kt++) {
        __syncthreads();

        // load 3 tiles (128 rows x 32 bf16): 512 uint4 per tile, 2 per thread
#pragma unroll
        for (int u = 0; u < 2; u++) {
            int li  = tid + u * 256;
            int row = li >> 2;
            int q   = li & 3;
            *(uint4*)(smem + row * DROW_B + q * 16) =
                *(const uint4*)(S + (size_t)(m0 + row) * D_SZ + kt * 32 + q * 8);
            *(uint4*)(smem + DTILE_B + row * DROW_B + q * 16) =
                *(const uint4*)(Wh + (size_t)(n0 + row) * D_SZ + kt * 32 + q * 8);
            *(uint4*)(smem + 2 * DTILE_B + row * DROW_B + q * 16) =
                *(const uint4*)(Wl + (size_t)(n0 + row) * D_SZ + kt * 32 + q * 8);
        }
        __syncthreads();

#pragma unroll
        for (int c = 0; c < 2; c++) {
            // A fragments (spk): 4 m-frags of 16 rows
            uint32_t af[4][4];
#pragma unroll
            for (int mf = 0; mf < 4; mf++) {
                int row = wm * 64 + mf * 16 + fr;
                const char* p = smem + row * DROW_B + (c * 16 + kp * 2) * 2;
                af[mf][0] = *(const uint32_t*)(p);
                af[mf][1] = *(const uint32_t*)(p + 8 * DROW_B);
                af[mf][2] = *(const uint32_t*)(p + 16);
                af[mf][3] = *(const uint32_t*)(p + 8 * DROW_B + 16);
            }
            // B fragments: Wh and Wl, 4 n-frags of 8 cols each
            uint32_t bh[4][2], bl[4][2];
#pragma unroll
            for (int nf = 0; nf < 4; nf++) {
                int n = wn * 32 + nf * 8 + fr;
                const char* ph = smem + DTILE_B + n * DROW_B + (c * 16 + kp * 2) * 2;
                const char* pl = smem + 2 * DTILE_B + n * DROW_B + (c * 16 + kp * 2) * 2;
                bh[nf][0] = *(const uint32_t*)(ph);
                bh[nf][1] = *(const uint32_t*)(ph + 16);
                bl[nf][0] = *(const uint32_t*)(pl);
                bl[nf][1] = *(const uint32_t*)(pl + 16);
            }
#pragma unroll
            for (int mf = 0; mf < 4; mf++)
#pragma unroll
                for (int nf = 0; nf < 4; nf++) {
                    mma16816(acc[mf][nf], af[mf], bh[nf]);
                    mma16816(acc[mf][nf], af[mf], bl[nf]);
                }
        }
    }

    // epilogue: bias + sigmoid, store
#pragma unroll
    for (int mf = 0; mf < 4; mf++) {
#pragma unroll
        for (int nf = 0; nf < 4; nf++) {
            int row0 = m0 + wm * 64 + mf * 16 + fr;
            int col  = n0 + wn * 32 + nf * 8 + kp * 2;
            float b0 = bias[col], b1 = bias[col + 1];
            float2 v0, v1;
            v0.x = 1.0f / (1.0f + expf(-(acc[mf][nf][0] + b0)));
            v0.y = 1.0f / (1.0f + expf(-(acc[mf][nf][1] + b1)));
            v1.x = 1.0f / (1.0f + expf(-(acc[mf][nf][2] + b0)));
            v1.y = 1.0f / (1.0f + expf(-(acc[mf][nf][3] + b1)));
            *(float2*)(dec + (size_t)row0 * D_SZ + col) = v0;
            *(float2*)(dec + (size_t)(row0 + 8) * D_SZ + col) = v1;
        }
    }
}

// ---------------------------------------------------------------------------
extern "C" void kernel_launch(void* const* d_in, const int* in_sizes, int n_in,
                              void* d_out, int out_size)
{
    const float* x     = (const float*)d_in[0];
    const float* W_enc = (const float*)d_in[1];
    const float* b_enc = (const float*)d_in[2];
    const float* W_dec = (const float*)d_in[3];
    const float* b_dec = (const float*)d_in[4];
    const float* beta  = (const float*)d_in[5];

    float* out = (float*)d_out;
    float* spk = out;                                   // [T,B,D]
    float* dec = out + (size_t)M_TOTAL * D_SZ;          // [T,B,D]

    float* enc; __nv_bfloat16 *spkb, *Wh, *Wl;
    cudaGetSymbolAddress((void**)&enc, g_enc);
    cudaGetSymbolAddress((void**)&spkb, g_spkb);
    cudaGetSymbolAddress((void**)&Wh, g_Wh);
    cudaGetSymbolAddress((void**)&Wl, g_Wl);

    cudaFuncSetAttribute(dec_mma_k, cudaFuncAttributeMaxDynamicSharedMemorySize,
                         DEC_SMEM);

    dim3 gemm_grid(D_SZ / 128, M_TOTAL / 128);          // (16, 200)

    // 1) encoder GEMM (bit-exact 8x256 blocked chain) -> g_enc
    gemm_enc_k<<<gemm_grid, 256>>>(x, W_enc, b_enc, enc);

    // 2) W_dec split (runs while encoder occupies... sequential stream, cheap)
    split_wdec_k<<<(int)(((size_t)D_SZ * D_SZ) / 256), 256>>>(W_dec, Wh, Wl);

    // 3) LIF scan -> spk fp32 (d_out) + spk bf16 (scratch)
    lif_scan_k<<<BD / 256, 256>>>(enc, beta, spk, spkb);

    // 4) decoder GEMM via HMMA bf16x2 (bias + sigmoid) -> dec
    dec_mma_k<<<gemm_grid, 256, DEC_SMEM>>>(spkb, Wh, Wl, b_dec, dec);
}